// round 1
// baseline (speedup 1.0000x reference)
#include <cuda_runtime.h>
#include <cstddef>

#define BATCH   2
#define CHN     512
#define NSP     4096            // 64*64 spatial
#define NGROUPS 32
#define CPG     (CHN / NGROUPS) // 16
#define EPSV    1e-6f
#define SM_SCALE 0.04419417382415922f   // 512^-0.5

// ---------------- scratch (device globals; no allocation) ----------------
__device__ __align__(16) float g_hn[(size_t)BATCH * CHN * NSP];
__device__ __align__(16) float g_q [(size_t)BATCH * CHN * NSP];
__device__ __align__(16) float g_k [(size_t)BATCH * CHN * NSP];
__device__ __align__(16) float g_v [(size_t)BATCH * CHN * NSP];
__device__ __align__(16) float g_S [(size_t)BATCH * NSP * NSP];   // 134 MB
__device__ __align__(16) float g_h [(size_t)BATCH * CHN * NSP];

// ---------------- GroupNorm ----------------
// grid = BATCH*NGROUPS blocks, 1024 threads. Two-pass: mean/var then normalize.
__global__ __launch_bounds__(1024) void gn_kernel(
    const float* __restrict__ x,
    const float* __restrict__ gamma,
    const float* __restrict__ beta)
{
    const int bg = blockIdx.x;
    const int b  = bg / NGROUPS;
    const int g  = bg % NGROUPS;
    const int len = CPG * NSP;                       // 65536
    const float* xp = x   + ((size_t)b * CHN + g * CPG) * NSP;
    float*       hp = g_hn + ((size_t)b * CHN + g * CPG) * NSP;

    float s = 0.f, ss = 0.f;
    for (int i = threadIdx.x * 4; i < len; i += blockDim.x * 4) {
        float4 v = *reinterpret_cast<const float4*>(xp + i);
        s  += v.x + v.y + v.z + v.w;
        ss += v.x * v.x + v.y * v.y + v.z * v.z + v.w * v.w;
    }
    __shared__ float rs[32], rss[32];
    #pragma unroll
    for (int o = 16; o; o >>= 1) {
        s  += __shfl_down_sync(0xffffffffu, s,  o);
        ss += __shfl_down_sync(0xffffffffu, ss, o);
    }
    const int warp = threadIdx.x >> 5, lane = threadIdx.x & 31;
    if (lane == 0) { rs[warp] = s; rss[warp] = ss; }
    __syncthreads();
    const int nw = blockDim.x >> 5;  // 32
    if (warp == 0) {
        s  = (lane < nw) ? rs[lane]  : 0.f;
        ss = (lane < nw) ? rss[lane] : 0.f;
        #pragma unroll
        for (int o = 16; o; o >>= 1) {
            s  += __shfl_down_sync(0xffffffffu, s,  o);
            ss += __shfl_down_sync(0xffffffffu, ss, o);
        }
        if (lane == 0) { rs[0] = s; rss[0] = ss; }
    }
    __syncthreads();
    const float mean = rs[0] / (float)len;
    const float var  = rss[0] / (float)len - mean * mean;
    const float inv  = rsqrtf(var + EPSV);

    for (int i = threadIdx.x * 4; i < len; i += blockDim.x * 4) {
        const int ch = g * CPG + i / NSP;            // 4 elems share channel (NSP%4==0)
        const float ga = gamma[ch] * inv, be = beta[ch];
        float4 v = *reinterpret_cast<const float4*>(xp + i);
        float4 o4;
        o4.x = (v.x - mean) * ga + be;
        o4.y = (v.y - mean) * ga + be;
        o4.z = (v.z - mean) * ga + be;
        o4.w = (v.w - mean) * ga + be;
        *reinterpret_cast<float4*>(hp + i) = o4;
    }
}

// ---------------- SGEMM building blocks ----------------
// 128x128x16 tile, 256 threads, 8x8 register micro-tile.
#define BM 128
#define BN 128
#define BK 16
#define SPAD 4   // smem row padding (keeps float4 alignment: 132 % 4 == 0)

// C[m][n] = sum_k A[m][k] * B[k][n] (+bias[m]) (+resid[m][n])
// A: MxK row-major (shared across z). B,C,resid offset by blockIdx.z strides.
__global__ __launch_bounds__(256) void sgemm_nn(
    const float* __restrict__ A, const float* __restrict__ B,
    const float* __restrict__ bias, const float* __restrict__ resid,
    float* __restrict__ C, int M, int N, int K,
    size_t strideB, size_t strideC)
{
    __shared__ float As[BK][BM + SPAD];
    __shared__ float Bs[BK][BN + SPAD];
    const int bx = blockIdx.x, by = blockIdx.y;
    B += (size_t)blockIdx.z * strideB;
    C += (size_t)blockIdx.z * strideC;
    if (resid) resid += (size_t)blockIdx.z * strideC;

    const int tid = threadIdx.x;
    const int tx = tid & 15, ty = tid >> 4;
    float acc[8][8] = {};

    for (int k0 = 0; k0 < K; k0 += BK) {
        #pragma unroll
        for (int l = 0; l < 2; l++) {
            const int f = tid + l * 256;
            // A tile: 128 rows x 16 cols -> transpose into As
            const int ar = f >> 2, ac = (f & 3) * 4;
            float4 av = *reinterpret_cast<const float4*>(
                A + (size_t)(by * BM + ar) * K + k0 + ac);
            As[ac + 0][ar] = av.x; As[ac + 1][ar] = av.y;
            As[ac + 2][ar] = av.z; As[ac + 3][ar] = av.w;
            // B tile: 16 rows x 128 cols -> direct
            const int br = f >> 5, bc = (f & 31) * 4;
            *reinterpret_cast<float4*>(&Bs[br][bc]) =
                *reinterpret_cast<const float4*>(B + (size_t)(k0 + br) * N + bx * BN + bc);
        }
        __syncthreads();
        #pragma unroll
        for (int k = 0; k < BK; k++) {
            float a[8], bb[8];
            #pragma unroll
            for (int i = 0; i < 8; i++) a[i] = As[k][ty * 8 + i];
            #pragma unroll
            for (int j = 0; j < 8; j++) bb[j] = Bs[k][tx * 8 + j];
            #pragma unroll
            for (int i = 0; i < 8; i++)
                #pragma unroll
                for (int j = 0; j < 8; j++)
                    acc[i][j] += a[i] * bb[j];
        }
        __syncthreads();
    }
    #pragma unroll
    for (int i = 0; i < 8; i++) {
        const int row = by * BM + ty * 8 + i;
        const float bi = bias ? bias[row] : 0.f;
        #pragma unroll
        for (int j = 0; j < 8; j += 4) {
            const int col = bx * BN + tx * 8 + j;
            float4 r;
            r.x = acc[i][j + 0] + bi; r.y = acc[i][j + 1] + bi;
            r.z = acc[i][j + 2] + bi; r.w = acc[i][j + 3] + bi;
            if (resid) {
                float4 xv = *reinterpret_cast<const float4*>(resid + (size_t)row * N + col);
                r.x += xv.x; r.y += xv.y; r.z += xv.z; r.w += xv.w;
            }
            *reinterpret_cast<float4*>(C + (size_t)row * N + col) = r;
        }
    }
}

// C[m][n] = alpha * sum_k A[k][m] * B[k][n]   (A,B both K-major rows, lda/ldb row length)
__global__ __launch_bounds__(256) void sgemm_tn(
    const float* __restrict__ A, const float* __restrict__ B,
    float* __restrict__ C, int M, int N, int K, float alpha,
    size_t strideA, size_t strideB, size_t strideC)
{
    __shared__ float As[BK][BM + SPAD];
    __shared__ float Bs[BK][BN + SPAD];
    const int bx = blockIdx.x, by = blockIdx.y;
    A += (size_t)blockIdx.z * strideA;
    B += (size_t)blockIdx.z * strideB;
    C += (size_t)blockIdx.z * strideC;

    const int tid = threadIdx.x;
    const int tx = tid & 15, ty = tid >> 4;
    float acc[8][8] = {};

    for (int k0 = 0; k0 < K; k0 += BK) {
        #pragma unroll
        for (int l = 0; l < 2; l++) {
            const int f = tid + l * 256;
            const int kr = f >> 5, mc = (f & 31) * 4;
            *reinterpret_cast<float4*>(&As[kr][mc]) =
                *reinterpret_cast<const float4*>(A + (size_t)(k0 + kr) * M + by * BM + mc);
            *reinterpret_cast<float4*>(&Bs[kr][mc]) =
                *reinterpret_cast<const float4*>(B + (size_t)(k0 + kr) * N + bx * BN + mc);
        }
        __syncthreads();
        #pragma unroll
        for (int k = 0; k < BK; k++) {
            float a[8], bb[8];
            #pragma unroll
            for (int i = 0; i < 8; i++) a[i] = As[k][ty * 8 + i];
            #pragma unroll
            for (int j = 0; j < 8; j++) bb[j] = Bs[k][tx * 8 + j];
            #pragma unroll
            for (int i = 0; i < 8; i++)
                #pragma unroll
                for (int j = 0; j < 8; j++)
                    acc[i][j] += a[i] * bb[j];
        }
        __syncthreads();
    }
    #pragma unroll
    for (int i = 0; i < 8; i++) {
        const int row = by * BM + ty * 8 + i;
        #pragma unroll
        for (int j = 0; j < 8; j += 4) {
            const int col = bx * BN + tx * 8 + j;
            float4 r;
            r.x = acc[i][j + 0] * alpha; r.y = acc[i][j + 1] * alpha;
            r.z = acc[i][j + 2] * alpha; r.w = acc[i][j + 3] * alpha;
            *reinterpret_cast<float4*>(C + (size_t)row * N + col) = r;
        }
    }
}

// C[m][n] = sum_k A[m][k] * B[n][k]   (A MxK row-major, B NxK row-major)
__global__ __launch_bounds__(256) void sgemm_nt(
    const float* __restrict__ A, const float* __restrict__ B,
    float* __restrict__ C, int M, int N, int K,
    size_t strideA, size_t strideB, size_t strideC)
{
    __shared__ float As[BK][BM + SPAD];
    __shared__ float Bs[BK][BN + SPAD];
    const int bx = blockIdx.x, by = blockIdx.y;
    A += (size_t)blockIdx.z * strideA;
    B += (size_t)blockIdx.z * strideB;
    C += (size_t)blockIdx.z * strideC;

    const int tid = threadIdx.x;
    const int tx = tid & 15, ty = tid >> 4;
    float acc[8][8] = {};

    for (int k0 = 0; k0 < K; k0 += BK) {
        #pragma unroll
        for (int l = 0; l < 2; l++) {
            const int f = tid + l * 256;
            const int ar = f >> 2, ac = (f & 3) * 4;
            float4 av = *reinterpret_cast<const float4*>(
                A + (size_t)(by * BM + ar) * K + k0 + ac);
            As[ac + 0][ar] = av.x; As[ac + 1][ar] = av.y;
            As[ac + 2][ar] = av.z; As[ac + 3][ar] = av.w;
            const int br = f >> 2, bc = (f & 3) * 4;
            float4 bv = *reinterpret_cast<const float4*>(
                B + (size_t)(bx * BN + br) * K + k0 + bc);
            Bs[bc + 0][br] = bv.x; Bs[bc + 1][br] = bv.y;
            Bs[bc + 2][br] = bv.z; Bs[bc + 3][br] = bv.w;
        }
        __syncthreads();
        #pragma unroll
        for (int k = 0; k < BK; k++) {
            float a[8], bb[8];
            #pragma unroll
            for (int i = 0; i < 8; i++) a[i] = As[k][ty * 8 + i];
            #pragma unroll
            for (int j = 0; j < 8; j++) bb[j] = Bs[k][tx * 8 + j];
            #pragma unroll
            for (int i = 0; i < 8; i++)
                #pragma unroll
                for (int j = 0; j < 8; j++)
                    acc[i][j] += a[i] * bb[j];
        }
        __syncthreads();
    }
    #pragma unroll
    for (int i = 0; i < 8; i++) {
        const int row = by * BM + ty * 8 + i;
        #pragma unroll
        for (int j = 0; j < 8; j += 4) {
            const int col = bx * BN + tx * 8 + j;
            float4 r;
            r.x = acc[i][j + 0]; r.y = acc[i][j + 1];
            r.z = acc[i][j + 2]; r.w = acc[i][j + 3];
            *reinterpret_cast<float4*>(C + (size_t)row * N + col) = r;
        }
    }
}

// ---------------- row softmax over S (8192 rows x 4096) ----------------
__global__ __launch_bounds__(256) void softmax_kernel(float* __restrict__ Sbase)
{
    float* p = Sbase + (size_t)blockIdx.x * NSP;
    const int t = threadIdx.x;
    const int warp = t >> 5, lane = t & 31;
    __shared__ float red[8];

    float4 v[4];
    float mx = -3.4e38f;
    #pragma unroll
    for (int l = 0; l < 4; l++) {
        v[l] = *reinterpret_cast<float4*>(p + l * 1024 + t * 4);
        mx = fmaxf(mx, fmaxf(fmaxf(v[l].x, v[l].y), fmaxf(v[l].z, v[l].w)));
    }
    #pragma unroll
    for (int o = 16; o; o >>= 1) mx = fmaxf(mx, __shfl_xor_sync(0xffffffffu, mx, o));
    if (lane == 0) red[warp] = mx;
    __syncthreads();
    mx = red[0];
    #pragma unroll
    for (int w = 1; w < 8; w++) mx = fmaxf(mx, red[w]);
    __syncthreads();

    float s = 0.f;
    #pragma unroll
    for (int l = 0; l < 4; l++) {
        v[l].x = __expf(v[l].x - mx); v[l].y = __expf(v[l].y - mx);
        v[l].z = __expf(v[l].z - mx); v[l].w = __expf(v[l].w - mx);
        s += v[l].x + v[l].y + v[l].z + v[l].w;
    }
    #pragma unroll
    for (int o = 16; o; o >>= 1) s += __shfl_xor_sync(0xffffffffu, s, o);
    if (lane == 0) red[warp] = s;
    __syncthreads();
    s = red[0];
    #pragma unroll
    for (int w = 1; w < 8; w++) s += red[w];
    const float inv = 1.f / s;
    #pragma unroll
    for (int l = 0; l < 4; l++) {
        v[l].x *= inv; v[l].y *= inv; v[l].z *= inv; v[l].w *= inv;
        *reinterpret_cast<float4*>(p + l * 1024 + t * 4) = v[l];
    }
}

// ---------------- launch ----------------
extern "C" void kernel_launch(void* const* d_in, const int* in_sizes, int n_in,
                              void* d_out, int out_size)
{
    const float* x        = (const float*)d_in[0];
    const float* gn_gamma = (const float*)d_in[1];
    const float* gn_beta  = (const float*)d_in[2];
    const float* q_w      = (const float*)d_in[3];
    const float* q_b      = (const float*)d_in[4];
    const float* k_w      = (const float*)d_in[5];
    const float* k_b      = (const float*)d_in[6];
    const float* v_w      = (const float*)d_in[7];
    const float* v_b      = (const float*)d_in[8];
    const float* proj_w   = (const float*)d_in[9];
    const float* proj_b   = (const float*)d_in[10];
    float* out = (float*)d_out;

    float *hn, *q, *k, *v, *S, *h;
    cudaGetSymbolAddress((void**)&hn, g_hn);
    cudaGetSymbolAddress((void**)&q,  g_q);
    cudaGetSymbolAddress((void**)&k,  g_k);
    cudaGetSymbolAddress((void**)&v,  g_v);
    cudaGetSymbolAddress((void**)&S,  g_S);
    cudaGetSymbolAddress((void**)&h,  g_h);

    const size_t strideCN = (size_t)CHN * NSP;      // per-batch stride for [c][n] tensors
    const size_t strideNN = (size_t)NSP * NSP;      // per-batch stride for S

    // 1) GroupNorm
    gn_kernel<<<BATCH * NGROUPS, 1024>>>(x, gn_gamma, gn_beta);

    // 2) Q/K/V = W @ hn + b   : M=512, N=4096, K=512, per-batch
    dim3 gQKV(NSP / BN, CHN / BM, BATCH);
    sgemm_nn<<<gQKV, 256>>>(q_w, hn, q_b, nullptr, q, CHN, NSP, CHN, strideCN, strideCN);
    sgemm_nn<<<gQKV, 256>>>(k_w, hn, k_b, nullptr, k, CHN, NSP, CHN, strideCN, strideCN);
    sgemm_nn<<<gQKV, 256>>>(v_w, hn, v_b, nullptr, v, CHN, NSP, CHN, strideCN, strideCN);

    // 3) S[i][j] = scale * sum_c q[c][i] k[c][j]  : M=N=4096, K=512
    dim3 gS(NSP / BN, NSP / BM, BATCH);
    sgemm_tn<<<gS, 256>>>(q, k, S, NSP, NSP, CHN, SM_SCALE, strideCN, strideCN, strideNN);

    // 4) softmax rows
    softmax_kernel<<<BATCH * NSP, 256>>>(S);

    // 5) h[c][i] = sum_j v[c][j] P[i][j]  : M=512, N=4096, K=4096
    dim3 gO(NSP / BN, CHN / BM, BATCH);
    sgemm_nt<<<gO, 256>>>(v, S, h, CHN, NSP, NSP, strideCN, strideNN, strideCN);

    // 6) out = x + proj_w @ h + proj_b
    sgemm_nn<<<gQKV, 256>>>(proj_w, h, proj_b, x, out, CHN, NSP, CHN, strideCN, strideCN);
}

// round 3
// speedup vs baseline: 3.1600x; 3.1600x over previous
#include <cuda_runtime.h>
#include <cstdint>
#include <cstddef>

#define BATCH   2
#define CHN     512
#define NSP     4096
#define NGROUPS 32
#define CPG     16
#define EPSV    1e-6f
#define SM_SCALE 0.04419417382415922f   // 512^-0.5

// GEMM tiling
#define BMT 128
#define BNT 128
#define BKT 32
#define SROW 36                 // padded floats per smem row (144B, 16B-aligned, conflict-free)
#define STAGEF (128 * SROW)     // floats per operand per stage
#define SMEM_BYTES (4 * STAGEF * 4)   // 2 stages x (A+B) = 73728 B

// ---------------- scratch (device globals; no allocation) ----------------
__device__ __align__(16) float g_hn[(size_t)BATCH * NSP * CHN];   // token-major [b][n][c]
__device__ __align__(16) float g_q [(size_t)BATCH * NSP * CHN];   // token-major
__device__ __align__(16) float g_k [(size_t)BATCH * NSP * CHN];   // token-major
__device__ __align__(16) float g_v [(size_t)BATCH * CHN * NSP];   // channel-major [b][c][n]
__device__ __align__(16) float g_S [(size_t)BATCH * NSP * NSP];   // 134 MB
__device__ __align__(16) float g_h [(size_t)BATCH * NSP * CHN];   // token-major

// ---------------- small PTX helpers ----------------
__device__ __forceinline__ void cp16(uint32_t s, const void* g) {
    asm volatile("cp.async.ca.shared.global [%0], [%1], 16;\n" :: "r"(s), "l"(g));
}
__device__ __forceinline__ void cp_commit() {
    asm volatile("cp.async.commit_group;\n");
}
__device__ __forceinline__ void ldm4(uint32_t& r0, uint32_t& r1, uint32_t& r2, uint32_t& r3,
                                     uint32_t addr) {
    asm volatile("ldmatrix.sync.aligned.m8n8.x4.shared.b16 {%0,%1,%2,%3}, [%4];"
                 : "=r"(r0), "=r"(r1), "=r"(r2), "=r"(r3) : "r"(addr));
}
__device__ __forceinline__ uint32_t f2tf(uint32_t x) {
    uint32_t y; float f = __uint_as_float(x);
    asm("cvt.rna.tf32.f32 %0, %1;" : "=r"(y) : "f"(f));
    return y;
}
__device__ __forceinline__ void mma_tf32(float* c, const uint32_t* a, const uint32_t* b) {
    asm volatile(
        "mma.sync.aligned.m16n8k8.row.col.f32.tf32.tf32.f32 "
        "{%0,%1,%2,%3}, {%4,%5,%6,%7}, {%8,%9}, {%0,%1,%2,%3};"
        : "+f"(c[0]), "+f"(c[1]), "+f"(c[2]), "+f"(c[3])
        : "r"(a[0]), "r"(a[1]), "r"(a[2]), "r"(a[3]), "r"(b[0]), "r"(b[1]));
}

// ---------------- universal NT GEMM: D[m][n] = alpha * sum_k A[m][k]*B[n][k] ----------------
// + optional rowbias[m], colbias[n], resid[m][n]. All dims multiples of tile.
__global__ __launch_bounds__(256, 2) void mma_nt(
    const float* __restrict__ A, const float* __restrict__ B, float* __restrict__ D,
    const float* __restrict__ rowb, const float* __restrict__ colb,
    const float* __restrict__ resid,
    int M, int N, int K, float alpha,
    size_t zA, size_t zB, size_t zD)
{
    extern __shared__ float smem[];
    A += zA * blockIdx.z;  B += zB * blockIdx.z;  D += zD * blockIdx.z;
    if (resid) resid += zD * blockIdx.z;

    const int tid = threadIdx.x, lane = tid & 31, wid = tid >> 5;
    const int wm = wid >> 2, wn = wid & 3;              // warp grid 2x4, warp tile 64x32
    const int bM = blockIdx.y * BMT, bN = blockIdx.x * BNT;
    const uint32_t sbase = (uint32_t)__cvta_generic_to_shared(smem);

    // per-lane ldmatrix address components
    const int l8 = lane & 7, lg = lane >> 3;
    const int arow = wm * 64 + l8 + (lg & 1) * 8;       // A quadrant rows
    const int acol = (lg >> 1) * 4;                     // A quadrant k-offset
    const int brow = wn * 32 + l8 + (lg >> 1) * 8;      // B quadrant rows (n)
    const int bcol = (lg & 1) * 4;                      // B quadrant k-offset

    const int ldrow = tid >> 3, ldc16 = tid & 7;        // cp.async mapping

    float acc[4][4][4];
    #pragma unroll
    for (int i = 0; i < 4; i++)
        #pragma unroll
        for (int j = 0; j < 4; j++)
            #pragma unroll
            for (int t = 0; t < 4; t++) acc[i][j][t] = 0.f;

    auto load_tile = [&](int kt, int s) {
        const int k0 = kt * BKT;
        #pragma unroll
        for (int i = 0; i < 4; i++) {
            const int row = ldrow + i * 32;             // 4 x 32 rows per pass = 128
            cp16(sbase + (uint32_t)((s * STAGEF + row * SROW + ldc16 * 4) * 4),
                 A + (size_t)(bM + row) * K + k0 + ldc16 * 4);
            cp16(sbase + (uint32_t)(((2 + s) * STAGEF + row * SROW + ldc16 * 4) * 4),
                 B + (size_t)(bN + row) * K + k0 + ldc16 * 4);
        }
        cp_commit();
    };

    auto compute = [&](int s) {
        const uint32_t aB = sbase + (uint32_t)(s * STAGEF * 4);
        const uint32_t bB = sbase + (uint32_t)((2 + s) * STAGEF * 4);
        #pragma unroll
        for (int ks = 0; ks < 4; ks++) {
            uint32_t af[4][4];
            #pragma unroll
            for (int mt = 0; mt < 4; mt++) {
                ldm4(af[mt][0], af[mt][1], af[mt][2], af[mt][3],
                     aB + (uint32_t)((((arow + mt * 16) * SROW) + ks * 8 + acol) * 4));
                #pragma unroll
                for (int t = 0; t < 4; t++) af[mt][t] = f2tf(af[mt][t]);
            }
            uint32_t bf[4][2];
            #pragma unroll
            for (int nt2 = 0; nt2 < 2; nt2++) {
                ldm4(bf[2 * nt2][0], bf[2 * nt2][1], bf[2 * nt2 + 1][0], bf[2 * nt2 + 1][1],
                     bB + (uint32_t)((((brow + nt2 * 16) * SROW) + ks * 8 + bcol) * 4));
            }
            #pragma unroll
            for (int nt = 0; nt < 4; nt++) {
                bf[nt][0] = f2tf(bf[nt][0]); bf[nt][1] = f2tf(bf[nt][1]);
            }
            #pragma unroll
            for (int mt = 0; mt < 4; mt++)
                #pragma unroll
                for (int nt = 0; nt < 4; nt++)
                    mma_tf32(acc[mt][nt], af[mt], bf[nt]);
        }
    };

    const int KT = K / BKT;
    load_tile(0, 0);
    for (int kt = 0; kt < KT; kt++) {
        const int s = kt & 1;
        if (kt + 1 < KT) {
            load_tile(kt + 1, s ^ 1);
            asm volatile("cp.async.wait_group 1;\n");
        } else {
            asm volatile("cp.async.wait_group 0;\n");
        }
        __syncthreads();
        compute(s);
        __syncthreads();
    }

    // epilogue
    const int q4 = lane >> 2, cp2 = (lane & 3) * 2;
    #pragma unroll
    for (int mt = 0; mt < 4; mt++) {
        const int r0 = bM + wm * 64 + mt * 16 + q4;
        const int r1 = r0 + 8;
        const float rb0 = rowb ? rowb[r0] : 0.f;
        const float rb1 = rowb ? rowb[r1] : 0.f;
        #pragma unroll
        for (int nt = 0; nt < 4; nt++) {
            const int c = bN + wn * 32 + nt * 8 + cp2;
            float v00 = acc[mt][nt][0] * alpha + rb0;
            float v01 = acc[mt][nt][1] * alpha + rb0;
            float v10 = acc[mt][nt][2] * alpha + rb1;
            float v11 = acc[mt][nt][3] * alpha + rb1;
            if (colb) {
                const float cb0 = colb[c], cb1 = colb[c + 1];
                v00 += cb0; v01 += cb1; v10 += cb0; v11 += cb1;
            }
            if (resid) {
                float2 x0 = *reinterpret_cast<const float2*>(resid + (size_t)r0 * N + c);
                float2 x1 = *reinterpret_cast<const float2*>(resid + (size_t)r1 * N + c);
                v00 += x0.x; v01 += x0.y; v10 += x1.x; v11 += x1.y;
            }
            float2 o0; o0.x = v00; o0.y = v01;
            float2 o1; o1.x = v10; o1.y = v11;
            *reinterpret_cast<float2*>(D + (size_t)r0 * N + c) = o0;
            *reinterpret_cast<float2*>(D + (size_t)r1 * N + c) = o1;
        }
    }
}

// ---------------- GroupNorm -> token-major hn_t[b][n][c] ----------------
__global__ __launch_bounds__(1024) void gn_t_kernel(
    const float* __restrict__ x,
    const float* __restrict__ gamma,
    const float* __restrict__ beta)
{
    const int bg = blockIdx.x;
    const int b = bg / NGROUPS, g = bg % NGROUPS;
    const int len = CPG * NSP;                          // 65536
    const float* xp = x + ((size_t)b * CHN + g * CPG) * NSP;
    float* hp = g_hn + (size_t)b * NSP * CHN;           // token-major base

    // pass 1: mean / var
    float s = 0.f, ss = 0.f;
    for (int i = threadIdx.x * 4; i < len; i += blockDim.x * 4) {
        float4 v = *reinterpret_cast<const float4*>(xp + i);
        s  += v.x + v.y + v.z + v.w;
        ss += v.x * v.x + v.y * v.y + v.z * v.z + v.w * v.w;
    }
    __shared__ float rs[32], rss[32];
    #pragma unroll
    for (int o = 16; o; o >>= 1) {
        s  += __shfl_down_sync(0xffffffffu, s,  o);
        ss += __shfl_down_sync(0xffffffffu, ss, o);
    }
    const int warp = threadIdx.x >> 5, lane = threadIdx.x & 31;
    if (lane == 0) { rs[warp] = s; rss[warp] = ss; }
    __syncthreads();
    if (warp == 0) {
        s  = (lane < 32) ? rs[lane]  : 0.f;
        ss = (lane < 32) ? rss[lane] : 0.f;
        #pragma unroll
        for (int o = 16; o; o >>= 1) {
            s  += __shfl_down_sync(0xffffffffu, s,  o);
            ss += __shfl_down_sync(0xffffffffu, ss, o);
        }
        if (lane == 0) { rs[0] = s; rss[0] = ss; }
    }
    __syncthreads();
    const float mean = rs[0] / (float)len;
    const float var  = rss[0] / (float)len - mean * mean;
    const float inv  = rsqrtf(var + EPSV);
    __syncthreads();

    // pass 2: tiled transpose write (16 channels x 256 tokens per tile)
    __shared__ float tile[CPG][257];
    const int cc_w = threadIdx.x & 15;                  // write-phase channel
    const float ga = gamma[g * CPG + cc_w] * inv;
    const float be = beta[g * CPG + cc_w];

    for (int t16 = 0; t16 < 16; t16++) {
        const int n0 = t16 * 256;
        #pragma unroll
        for (int j = 0; j < 4; j++) {
            const int idx = threadIdx.x + j * 1024;
            const int cc = idx >> 8, nn = idx & 255;
            tile[cc][nn] = xp[(size_t)cc * NSP + n0 + nn];
        }
        __syncthreads();
        #pragma unroll
        for (int j = 0; j < 4; j++) {
            const int idx = threadIdx.x + j * 1024;
            const int n = idx >> 4;                     // 0..255
            hp[(size_t)(n0 + n) * CHN + g * CPG + cc_w] =
                (tile[cc_w][n] - mean) * ga + be;
        }
        __syncthreads();
    }
}

// ---------------- row softmax over S (8192 rows x 4096) ----------------
__global__ __launch_bounds__(256) void softmax_kernel(float* __restrict__ Sbase)
{
    float* p = Sbase + (size_t)blockIdx.x * NSP;
    const int t = threadIdx.x;
    const int warp = t >> 5, lane = t & 31;
    __shared__ float red[8];

    float4 v[4];
    float mx = -3.4e38f;
    #pragma unroll
    for (int l = 0; l < 4; l++) {
        v[l] = *reinterpret_cast<float4*>(p + l * 1024 + t * 4);
        mx = fmaxf(mx, fmaxf(fmaxf(v[l].x, v[l].y), fmaxf(v[l].z, v[l].w)));
    }
    #pragma unroll
    for (int o = 16; o; o >>= 1) mx = fmaxf(mx, __shfl_xor_sync(0xffffffffu, mx, o));
    if (lane == 0) red[warp] = mx;
    __syncthreads();
    mx = red[0];
    #pragma unroll
    for (int w = 1; w < 8; w++) mx = fmaxf(mx, red[w]);
    __syncthreads();

    float s = 0.f;
    #pragma unroll
    for (int l = 0; l < 4; l++) {
        v[l].x = __expf(v[l].x - mx); v[l].y = __expf(v[l].y - mx);
        v[l].z = __expf(v[l].z - mx); v[l].w = __expf(v[l].w - mx);
        s += v[l].x + v[l].y + v[l].z + v[l].w;
    }
    #pragma unroll
    for (int o = 16; o; o >>= 1) s += __shfl_xor_sync(0xffffffffu, s, o);
    if (lane == 0) red[warp] = s;
    __syncthreads();
    s = red[0];
    #pragma unroll
    for (int w = 1; w < 8; w++) s += red[w];
    const float inv = 1.f / s;
    #pragma unroll
    for (int l = 0; l < 4; l++) {
        v[l].x *= inv; v[l].y *= inv; v[l].z *= inv; v[l].w *= inv;
        *reinterpret_cast<float4*>(p + l * 1024 + t * 4) = v[l];
    }
}

// ---------------- launch ----------------
extern "C" void kernel_launch(void* const* d_in, const int* in_sizes, int n_in,
                              void* d_out, int out_size)
{
    const float* x        = (const float*)d_in[0];
    const float* gn_gamma = (const float*)d_in[1];
    const float* gn_beta  = (const float*)d_in[2];
    const float* q_w      = (const float*)d_in[3];
    const float* q_b      = (const float*)d_in[4];
    const float* k_w      = (const float*)d_in[5];
    const float* k_b      = (const float*)d_in[6];
    const float* v_w      = (const float*)d_in[7];
    const float* v_b      = (const float*)d_in[8];
    const float* proj_w   = (const float*)d_in[9];
    const float* proj_b   = (const float*)d_in[10];
    float* out = (float*)d_out;

    float *hn, *q, *k, *v, *S, *h;
    cudaGetSymbolAddress((void**)&hn, g_hn);
    cudaGetSymbolAddress((void**)&q,  g_q);
    cudaGetSymbolAddress((void**)&k,  g_k);
    cudaGetSymbolAddress((void**)&v,  g_v);
    cudaGetSymbolAddress((void**)&S,  g_S);
    cudaGetSymbolAddress((void**)&h,  g_h);

    cudaFuncSetAttribute(mma_nt, cudaFuncAttributeMaxDynamicSharedMemorySize, SMEM_BYTES);

    const size_t CN = (size_t)CHN * NSP;   // per-batch stride for [n][c] / [c][n]
    const size_t NN = (size_t)NSP * NSP;   // per-batch stride for S

    // 1) GroupNorm -> hn_t[b][n][c]
    gn_t_kernel<<<BATCH * NGROUPS, 1024>>>(x, gn_gamma, gn_beta);

    // 2) q_t[n][co] = hn_t[n][:] . q_w[co][:]  (M=4096, N=512, K=512), colbias q_b
    mma_nt<<<dim3(CHN / BNT, NSP / BMT, BATCH), 256, SMEM_BYTES>>>(
        hn, q_w, q, nullptr, q_b, nullptr, NSP, CHN, CHN, 1.f, CN, 0, CN);
    mma_nt<<<dim3(CHN / BNT, NSP / BMT, BATCH), 256, SMEM_BYTES>>>(
        hn, k_w, k, nullptr, k_b, nullptr, NSP, CHN, CHN, 1.f, CN, 0, CN);
    // v[c][n] = v_w[c][:] . hn_t[n][:]  (M=512, N=4096, K=512), rowbias v_b
    mma_nt<<<dim3(NSP / BNT, CHN / BMT, BATCH), 256, SMEM_BYTES>>>(
        v_w, hn, v, v_b, nullptr, nullptr, CHN, NSP, CHN, 1.f, 0, CN, CN);

    // 3) S[i][j] = scale * q_t[i][:] . k_t[j][:]  (M=N=4096, K=512)
    mma_nt<<<dim3(NSP / BNT, NSP / BMT, BATCH), 256, SMEM_BYTES>>>(
        q, k, S, nullptr, nullptr, nullptr, NSP, NSP, CHN, SM_SCALE, CN, CN, NN);

    // 4) softmax rows
    softmax_kernel<<<BATCH * NSP, 256>>>(S);

    // 5) h_t[i][c] = P[i][:] . v[c][:]  (M=4096, N=512, K=4096)
    mma_nt<<<dim3(CHN / BNT, NSP / BMT, BATCH), 256, SMEM_BYTES>>>(
        S, v, h, nullptr, nullptr, nullptr, NSP, CHN, NSP, 1.f, NN, CN, CN);

    // 6) out[co][n] = proj_w[co][:] . h_t[n][:] + proj_b[co] + x[co][n]
    mma_nt<<<dim3(NSP / BNT, CHN / BMT, BATCH), 256, SMEM_BYTES>>>(
        proj_w, h, out, proj_b, nullptr, x, CHN, NSP, CHN, 1.f, 0, CN, CN);
}

// round 5
// speedup vs baseline: 5.9663x; 1.8881x over previous
#include <cuda_runtime.h>
#include <cuda_bf16.h>
#include <cstdint>
#include <cstddef>

#define BATCH   2
#define CHN     512
#define NSP     4096
#define NGROUPS 32
#define CPG     16
#define EPSV    1e-6f
#define SM_SCALE 0.04419417382415922f   // 512^-0.5

// GEMM tiling: 128x128x64, bf16, XOR-swizzled 128B smem rows
#define BMT 128
#define BNT 128
#define BKT 64
#define STG_B 16384                  // bytes per operand per stage (128 rows x 128B)
#define SMEM_BYTES (4 * STG_B)       // 2 stages x (A+B) = 64 KB

// ---------------- scratch (device globals; no allocation) ----------------
__device__ __align__(16) __nv_bfloat16 g_hn[(size_t)BATCH * NSP * CHN];  // [b][n][c]
__device__ __align__(16) __nv_bfloat16 g_q [(size_t)BATCH * NSP * CHN];
__device__ __align__(16) __nv_bfloat16 g_k [(size_t)BATCH * NSP * CHN];
__device__ __align__(16) __nv_bfloat16 g_v [(size_t)BATCH * CHN * NSP];  // [b][c][n]
__device__ __align__(16) __nv_bfloat16 g_h [(size_t)BATCH * NSP * CHN];
__device__ __align__(16) float         g_S [(size_t)BATCH * NSP * NSP];  // 134 MB
__device__ __align__(16) __nv_bfloat16 g_P [(size_t)BATCH * NSP * NSP];  // 67 MB
__device__ __align__(16) __nv_bfloat16 g_wq[CHN * CHN];
__device__ __align__(16) __nv_bfloat16 g_wk[CHN * CHN];
__device__ __align__(16) __nv_bfloat16 g_wv[CHN * CHN];
__device__ __align__(16) __nv_bfloat16 g_wp[CHN * CHN];

// ---------------- PTX helpers ----------------
__device__ __forceinline__ void cp16(uint32_t s, const void* g) {
    asm volatile("cp.async.ca.shared.global [%0], [%1], 16;\n" :: "r"(s), "l"(g));
}
__device__ __forceinline__ void ldm4(uint32_t& r0, uint32_t& r1, uint32_t& r2, uint32_t& r3,
                                     uint32_t addr) {
    asm volatile("ldmatrix.sync.aligned.m8n8.x4.shared.b16 {%0,%1,%2,%3}, [%4];"
                 : "=r"(r0), "=r"(r1), "=r"(r2), "=r"(r3) : "r"(addr));
}
__device__ __forceinline__ void mma_bf16(float* c, const uint32_t* a, const uint32_t* b) {
    asm volatile(
        "mma.sync.aligned.m16n8k16.row.col.f32.bf16.bf16.f32 "
        "{%0,%1,%2,%3}, {%4,%5,%6,%7}, {%8,%9}, {%0,%1,%2,%3};"
        : "+f"(c[0]), "+f"(c[1]), "+f"(c[2]), "+f"(c[3])
        : "r"(a[0]), "r"(a[1]), "r"(a[2]), "r"(a[3]), "r"(b[0]), "r"(b[1]));
}

// ---------------- universal bf16 NT GEMM ----------------
// D[m][n] = alpha * sum_k A[m][k]*B[n][k] (+rowb[m]) (+colb[n]) (+resid[m][n])
// Output: Df (fp32) if non-null, else Dbf (bf16). Dims multiples of tile sizes.
__global__ __launch_bounds__(256, 2) void bgemm_nt(
    const __nv_bfloat16* __restrict__ A, const __nv_bfloat16* __restrict__ B,
    float* __restrict__ Df, __nv_bfloat16* __restrict__ Dbf,
    const float* __restrict__ rowb, const float* __restrict__ colb,
    const float* __restrict__ resid,
    int M, int N, int K, float alpha,
    size_t zA, size_t zB, size_t zD)
{
    extern __shared__ char smem[];
    A += zA * blockIdx.z;  B += zB * blockIdx.z;
    if (Df)    Df  += zD * blockIdx.z;
    if (Dbf)   Dbf += zD * blockIdx.z;
    if (resid) resid += zD * blockIdx.z;

    const int tid = threadIdx.x, lane = tid & 31, wid = tid >> 5;
    const int wm = wid >> 2, wn = wid & 3;              // warps 2x4; warp tile 64x32
    const int bM = blockIdx.y * BMT, bN = blockIdx.x * BNT;
    const uint32_t sbase = (uint32_t)__cvta_generic_to_shared(smem);

    // ldmatrix per-lane row/chunk components
    const int l8 = lane & 7;
    const int a_row = wm * 64 + l8 + ((lane >> 3) & 1) * 8;   // + mt*16
    const int a_csel = lane >> 4;                             // k8 selector (0/1)
    const int b_row = wn * 32 + l8 + (lane >> 4) * 8;         // + nt2*16
    const int b_csel = (lane >> 3) & 1;
    const int a_r7 = a_row & 7, b_r7 = b_row & 7;             // invariant under +16

    float acc[4][4][4];
    #pragma unroll
    for (int i = 0; i < 4; i++)
        #pragma unroll
        for (int j = 0; j < 4; j++)
            #pragma unroll
            for (int t = 0; t < 4; t++) acc[i][j][t] = 0.f;

    auto load_tile = [&](int kt, int s) {
        const int k0 = kt * BKT;
        #pragma unroll
        for (int i = 0; i < 4; i++) {
            const int id = tid + i * 256;                // 1024 chunks per operand
            const int row = id >> 3, c = id & 7;
            const uint32_t so = (uint32_t)(row * 128 + ((c ^ (row & 7)) << 4));
            cp16(sbase + (uint32_t)(s * STG_B) + so,
                 A + (size_t)(bM + row) * K + k0 + c * 8);
            cp16(sbase + (uint32_t)(2 * STG_B + s * STG_B) + so,
                 B + (size_t)(bN + row) * K + k0 + c * 8);
        }
        asm volatile("cp.async.commit_group;\n");
    };

    auto compute = [&](int s) {
        const uint32_t aB = sbase + (uint32_t)(s * STG_B);
        const uint32_t bB = sbase + (uint32_t)(2 * STG_B + s * STG_B);
        #pragma unroll
        for (int ks = 0; ks < 4; ks++) {
            const int ac = ((ks * 2 + a_csel) ^ a_r7) << 4;
            const int bc = ((ks * 2 + b_csel) ^ b_r7) << 4;
            uint32_t af[4][4];
            #pragma unroll
            for (int mt = 0; mt < 4; mt++)
                ldm4(af[mt][0], af[mt][1], af[mt][2], af[mt][3],
                     aB + (uint32_t)((a_row + mt * 16) * 128 + ac));
            uint32_t bf[4][2];
            #pragma unroll
            for (int nt2 = 0; nt2 < 2; nt2++)
                ldm4(bf[2 * nt2][0], bf[2 * nt2][1], bf[2 * nt2 + 1][0], bf[2 * nt2 + 1][1],
                     bB + (uint32_t)((b_row + nt2 * 16) * 128 + bc));
            #pragma unroll
            for (int mt = 0; mt < 4; mt++)
                #pragma unroll
                for (int nt = 0; nt < 4; nt++)
                    mma_bf16(acc[mt][nt], af[mt], bf[nt]);
        }
    };

    const int KT = K / BKT;
    load_tile(0, 0);
    for (int kt = 0; kt < KT; kt++) {
        const int s = kt & 1;
        if (kt + 1 < KT) {
            load_tile(kt + 1, s ^ 1);
            asm volatile("cp.async.wait_group 1;\n");
        } else {
            asm volatile("cp.async.wait_group 0;\n");
        }
        __syncthreads();
        compute(s);
        __syncthreads();
    }

    // epilogue
    const int q4 = lane >> 2, cp2 = (lane & 3) * 2;
    #pragma unroll
    for (int mt = 0; mt < 4; mt++) {
        const int r0 = bM + wm * 64 + mt * 16 + q4;
        const int r1 = r0 + 8;
        const float rb0 = rowb ? rowb[r0] : 0.f;
        const float rb1 = rowb ? rowb[r1] : 0.f;
        #pragma unroll
        for (int nt = 0; nt < 4; nt++) {
            const int c = bN + wn * 32 + nt * 8 + cp2;
            float v00 = acc[mt][nt][0] * alpha + rb0;
            float v01 = acc[mt][nt][1] * alpha + rb0;
            float v10 = acc[mt][nt][2] * alpha + rb1;
            float v11 = acc[mt][nt][3] * alpha + rb1;
            if (colb) {
                const float cb0 = colb[c], cb1 = colb[c + 1];
                v00 += cb0; v01 += cb1; v10 += cb0; v11 += cb1;
            }
            if (resid) {
                float2 x0 = *reinterpret_cast<const float2*>(resid + (size_t)r0 * N + c);
                float2 x1 = *reinterpret_cast<const float2*>(resid + (size_t)r1 * N + c);
                v00 += x0.x; v01 += x0.y; v10 += x1.x; v11 += x1.y;
            }
            if (Df) {
                float2 o0; o0.x = v00; o0.y = v01;
                float2 o1; o1.x = v10; o1.y = v11;
                *reinterpret_cast<float2*>(Df + (size_t)r0 * N + c) = o0;
                *reinterpret_cast<float2*>(Df + (size_t)r1 * N + c) = o1;
            } else {
                *reinterpret_cast<__nv_bfloat162*>(Dbf + (size_t)r0 * N + c) =
                    __floats2bfloat162_rn(v00, v01);
                *reinterpret_cast<__nv_bfloat162*>(Dbf + (size_t)r1 * N + c) =
                    __floats2bfloat162_rn(v10, v11);
            }
        }
    }
}

// ---------------- fp32 -> bf16 weight conversion ----------------
__global__ __launch_bounds__(256) void f2bf_kernel(const float* __restrict__ src,
                                                   __nv_bfloat16* __restrict__ dst, int n)
{
    const int i = (blockIdx.x * 256 + threadIdx.x) * 4;
    if (i < n) {
        float4 v = *reinterpret_cast<const float4*>(src + i);
        __nv_bfloat162 lo = __floats2bfloat162_rn(v.x, v.y);
        __nv_bfloat162 hi = __floats2bfloat162_rn(v.z, v.w);
        uint2 o; o.x = *reinterpret_cast<uint32_t*>(&lo); o.y = *reinterpret_cast<uint32_t*>(&hi);
        *reinterpret_cast<uint2*>(dst + i) = o;
    }
}

// ---------------- GroupNorm -> bf16 token-major hn[b][n][c] ----------------
__global__ __launch_bounds__(1024) void gn_t_kernel(
    const float* __restrict__ x,
    const float* __restrict__ gamma,
    const float* __restrict__ beta)
{
    const int bg = blockIdx.x;
    const int b = bg / NGROUPS, g = bg % NGROUPS;
    const int len = CPG * NSP;
    const float* xp = x + ((size_t)b * CHN + g * CPG) * NSP;
    __nv_bfloat16* hp = g_hn + (size_t)b * NSP * CHN;

    float s = 0.f, ss = 0.f;
    for (int i = threadIdx.x * 4; i < len; i += blockDim.x * 4) {
        float4 v = *reinterpret_cast<const float4*>(xp + i);
        s  += v.x + v.y + v.z + v.w;
        ss += v.x * v.x + v.y * v.y + v.z * v.z + v.w * v.w;
    }
    __shared__ float rs[32], rss[32];
    #pragma unroll
    for (int o = 16; o; o >>= 1) {
        s  += __shfl_down_sync(0xffffffffu, s,  o);
        ss += __shfl_down_sync(0xffffffffu, ss, o);
    }
    const int warp = threadIdx.x >> 5, lane = threadIdx.x & 31;
    if (lane == 0) { rs[warp] = s; rss[warp] = ss; }
    __syncthreads();
    if (warp == 0) {
        s  = (lane < 32) ? rs[lane]  : 0.f;
        ss = (lane < 32) ? rss[lane] : 0.f;
        #pragma unroll
        for (int o = 16; o; o >>= 1) {
            s  += __shfl_down_sync(0xffffffffu, s,  o);
            ss += __shfl_down_sync(0xffffffffu, ss, o);
        }
        if (lane == 0) { rs[0] = s; rss[0] = ss; }
    }
    __syncthreads();
    const float mean = rs[0] / (float)len;
    const float var  = rss[0] / (float)len - mean * mean;
    const float inv  = rsqrtf(var + EPSV);
    __syncthreads();

    __shared__ float tile[CPG][257];
    const int cc_w = threadIdx.x & 15;
    const float ga = gamma[g * CPG + cc_w] * inv;
    const float be = beta[g * CPG + cc_w];

    for (int t16 = 0; t16 < 16; t16++) {
        const int n0 = t16 * 256;
        #pragma unroll
        for (int j = 0; j < 4; j++) {
            const int idx = threadIdx.x + j * 1024;
            const int cc = idx >> 8, nn = idx & 255;
            tile[cc][nn] = xp[(size_t)cc * NSP + n0 + nn];
        }
        __syncthreads();
        #pragma unroll
        for (int j = 0; j < 4; j++) {
            const int idx = threadIdx.x + j * 1024;
            const int n = idx >> 4;
            hp[(size_t)(n0 + n) * CHN + g * CPG + cc_w] =
                __float2bfloat16((tile[cc_w][n] - mean) * ga + be);
        }
        __syncthreads();
    }
}

// ---------------- row softmax: S fp32 -> P bf16 ----------------
__global__ __launch_bounds__(256) void softmax_kernel(
    const float* __restrict__ Sbase, __nv_bfloat16* __restrict__ Pbase)
{
    const float* p = Sbase + (size_t)blockIdx.x * NSP;
    __nv_bfloat16* po = Pbase + (size_t)blockIdx.x * NSP;
    const int t = threadIdx.x;
    const int warp = t >> 5, lane = t & 31;
    __shared__ float red[8];

    float4 v[4];
    float mx = -3.4e38f;
    #pragma unroll
    for (int l = 0; l < 4; l++) {
        v[l] = *reinterpret_cast<const float4*>(p + l * 1024 + t * 4);
        mx = fmaxf(mx, fmaxf(fmaxf(v[l].x, v[l].y), fmaxf(v[l].z, v[l].w)));
    }
    #pragma unroll
    for (int o = 16; o; o >>= 1) mx = fmaxf(mx, __shfl_xor_sync(0xffffffffu, mx, o));
    if (lane == 0) red[warp] = mx;
    __syncthreads();
    mx = red[0];
    #pragma unroll
    for (int w = 1; w < 8; w++) mx = fmaxf(mx, red[w]);
    __syncthreads();

    float s = 0.f;
    #pragma unroll
    for (int l = 0; l < 4; l++) {
        v[l].x = __expf(v[l].x - mx); v[l].y = __expf(v[l].y - mx);
        v[l].z = __expf(v[l].z - mx); v[l].w = __expf(v[l].w - mx);
        s += v[l].x + v[l].y + v[l].z + v[l].w;
    }
    #pragma unroll
    for (int o = 16; o; o >>= 1) s += __shfl_xor_sync(0xffffffffu, s, o);
    if (lane == 0) red[warp] = s;
    __syncthreads();
    s = red[0];
    #pragma unroll
    for (int w = 1; w < 8; w++) s += red[w];
    const float inv = 1.f / s;
    #pragma unroll
    for (int l = 0; l < 4; l++) {
        __nv_bfloat162 lo = __floats2bfloat162_rn(v[l].x * inv, v[l].y * inv);
        __nv_bfloat162 hi = __floats2bfloat162_rn(v[l].z * inv, v[l].w * inv);
        uint2 o; o.x = *reinterpret_cast<uint32_t*>(&lo); o.y = *reinterpret_cast<uint32_t*>(&hi);
        *reinterpret_cast<uint2*>(po + l * 1024 + t * 4) = o;
    }
}

// ---------------- launch ----------------
extern "C" void kernel_launch(void* const* d_in, const int* in_sizes, int n_in,
                              void* d_out, int out_size)
{
    const float* x        = (const float*)d_in[0];
    const float* gn_gamma = (const float*)d_in[1];
    const float* gn_beta  = (const float*)d_in[2];
    const float* q_w      = (const float*)d_in[3];
    const float* q_b      = (const float*)d_in[4];
    const float* k_w      = (const float*)d_in[5];
    const float* k_b      = (const float*)d_in[6];
    const float* v_w      = (const float*)d_in[7];
    const float* v_b      = (const float*)d_in[8];
    const float* proj_w   = (const float*)d_in[9];
    const float* proj_b   = (const float*)d_in[10];
    float* out = (float*)d_out;

    __nv_bfloat16 *hn, *q, *k, *v, *h, *P, *wq, *wk, *wv, *wp;
    float *S;
    cudaGetSymbolAddress((void**)&hn, g_hn);
    cudaGetSymbolAddress((void**)&q,  g_q);
    cudaGetSymbolAddress((void**)&k,  g_k);
    cudaGetSymbolAddress((void**)&v,  g_v);
    cudaGetSymbolAddress((void**)&h,  g_h);
    cudaGetSymbolAddress((void**)&S,  g_S);
    cudaGetSymbolAddress((void**)&P,  g_P);
    cudaGetSymbolAddress((void**)&wq, g_wq);
    cudaGetSymbolAddress((void**)&wk, g_wk);
    cudaGetSymbolAddress((void**)&wv, g_wv);
    cudaGetSymbolAddress((void**)&wp, g_wp);

    cudaFuncSetAttribute(bgemm_nt, cudaFuncAttributeMaxDynamicSharedMemorySize, SMEM_BYTES);

    const size_t CN = (size_t)CHN * NSP;
    const size_t NN = (size_t)NSP * NSP;
    const int WN = CHN * CHN;

    // 0) weights -> bf16
    f2bf_kernel<<<WN / 1024, 256>>>(q_w, wq, WN);
    f2bf_kernel<<<WN / 1024, 256>>>(k_w, wk, WN);
    f2bf_kernel<<<WN / 1024, 256>>>(v_w, wv, WN);
    f2bf_kernel<<<WN / 1024, 256>>>(proj_w, wp, WN);

    // 1) GroupNorm -> hn bf16 [b][n][c]
    gn_t_kernel<<<BATCH * NGROUPS, 1024>>>(x, gn_gamma, gn_beta);

    // 2) q[n][co] = hn[n][:] . wq[co][:] + q_b  (M=4096,N=512,K=512), bf16 out
    bgemm_nt<<<dim3(CHN / BNT, NSP / BMT, BATCH), 256, SMEM_BYTES>>>(
        hn, wq, nullptr, q, nullptr, q_b, nullptr, NSP, CHN, CHN, 1.f, CN, 0, CN);
    bgemm_nt<<<dim3(CHN / BNT, NSP / BMT, BATCH), 256, SMEM_BYTES>>>(
        hn, wk, nullptr, k, nullptr, k_b, nullptr, NSP, CHN, CHN, 1.f, CN, 0, CN);
    // v[c][n] = wv[c][:] . hn[n][:] + v_b  (M=512,N=4096,K=512), bf16 out
    bgemm_nt<<<dim3(NSP / BNT, CHN / BMT, BATCH), 256, SMEM_BYTES>>>(
        wv, hn, nullptr, v, v_b, nullptr, nullptr, CHN, NSP, CHN, 1.f, 0, CN, CN);

    // 3) S = scale * q . k^T  (M=N=4096,K=512), fp32 out
    bgemm_nt<<<dim3(NSP / BNT, NSP / BMT, BATCH), 256, SMEM_BYTES>>>(
        q, k, S, nullptr, nullptr, nullptr, nullptr, NSP, NSP, CHN, SM_SCALE, CN, CN, NN);

    // 4) softmax rows -> P bf16
    softmax_kernel<<<BATCH * NSP, 256>>>(S, P);

    // 5) h[i][c] = P[i][:] . v[c][:]  (M=4096,N=512,K=4096), bf16 out
    bgemm_nt<<<dim3(CHN / BNT, NSP / BMT, BATCH), 256, SMEM_BYTES>>>(
        P, v, nullptr, h, nullptr, nullptr, nullptr, NSP, CHN, NSP, 1.f, NN, CN, CN);

    // 6) out[co][n] = wp[co][:] . h[n][:] + proj_b[co] + x[co][n], fp32 out
    bgemm_nt<<<dim3(NSP / BNT, CHN / BMT, BATCH), 256, SMEM_BYTES>>>(
        wp, h, out, nullptr, proj_b, nullptr, x, CHN, NSP, CHN, 1.f, 0, CN, CN);
}

// round 7
// speedup vs baseline: 6.4929x; 1.0883x over previous
#include <cuda_runtime.h>
#include <cuda_bf16.h>
#include <cstdint>
#include <cstddef>

#define BATCH   2
#define CHN     512
#define NSP     4096
#define NGROUPS 32
#define CPG     16
#define EPSV    1e-6f
#define SM_SCALE 0.04419417382415922f   // 512^-0.5

// GEMM tiling: CTA 128x128x64, 4 warps (64x64 warp tiles), 3-stage cp.async
#define BMT 128
#define BNT 128
#define BKT 64
#define STG_B 16384u                 // bytes per operand per stage (128 rows x 128B)
#define NSTAGE 3
#define SMEM_BYTES (NSTAGE * 2 * 16384)   // 96 KB

// ---------------- scratch (device globals; no allocation) ----------------
__device__ __align__(16) __nv_bfloat16 g_hn[(size_t)BATCH * NSP * CHN];  // [b][n][c]
__device__ __align__(16) __nv_bfloat16 g_q [(size_t)BATCH * NSP * CHN];
__device__ __align__(16) __nv_bfloat16 g_k [(size_t)BATCH * NSP * CHN];
__device__ __align__(16) __nv_bfloat16 g_v [(size_t)BATCH * CHN * NSP];  // [b][c][n]
__device__ __align__(16) __nv_bfloat16 g_h [(size_t)BATCH * NSP * CHN];
__device__ __align__(16) float         g_S [(size_t)BATCH * NSP * NSP];  // 134 MB
__device__ __align__(16) __nv_bfloat16 g_P [(size_t)BATCH * NSP * NSP];  // 67 MB
__device__ __align__(16) __nv_bfloat16 g_wq[CHN * CHN];
__device__ __align__(16) __nv_bfloat16 g_wk[CHN * CHN];
__device__ __align__(16) __nv_bfloat16 g_wv[CHN * CHN];
__device__ __align__(16) __nv_bfloat16 g_wp[CHN * CHN];

// ---------------- PTX helpers ----------------
__device__ __forceinline__ void cp16(uint32_t s, const void* g) {
    asm volatile("cp.async.ca.shared.global [%0], [%1], 16;\n" :: "r"(s), "l"(g));
}
__device__ __forceinline__ void ldm4(uint32_t& r0, uint32_t& r1, uint32_t& r2, uint32_t& r3,
                                     uint32_t addr) {
    asm volatile("ldmatrix.sync.aligned.m8n8.x4.shared.b16 {%0,%1,%2,%3}, [%4];"
                 : "=r"(r0), "=r"(r1), "=r"(r2), "=r"(r3) : "r"(addr));
}
__device__ __forceinline__ void mma_bf16(float* c, const uint32_t* a, const uint32_t* b) {
    asm volatile(
        "mma.sync.aligned.m16n8k16.row.col.f32.bf16.bf16.f32 "
        "{%0,%1,%2,%3}, {%4,%5,%6,%7}, {%8,%9}, {%0,%1,%2,%3};"
        : "+f"(c[0]), "+f"(c[1]), "+f"(c[2]), "+f"(c[3])
        : "r"(a[0]), "r"(a[1]), "r"(a[2]), "r"(a[3]), "r"(b[0]), "r"(b[1]));
}

// ---------------- universal bf16 NT GEMM (mma.sync, 64x64 warp tiles) ----------------
// D[m][n] = alpha * sum_k A[m][k]*B[n][k] (+rowb[m]) (+colb[n]) (+resid[m][n])
// Output: Df (fp32) if non-null, else Dbf (bf16). Dims multiples of tile sizes.
__global__ __launch_bounds__(128, 2) void bgemm_nt(
    const __nv_bfloat16* __restrict__ A, const __nv_bfloat16* __restrict__ B,
    float* __restrict__ Df, __nv_bfloat16* __restrict__ Dbf,
    const float* __restrict__ rowb, const float* __restrict__ colb,
    const float* __restrict__ resid,
    int M, int N, int K, float alpha,
    size_t zA, size_t zB, size_t zD)
{
    extern __shared__ char smem[];
    A += zA * blockIdx.z;  B += zB * blockIdx.z;
    if (Df)    Df  += zD * blockIdx.z;
    if (Dbf)   Dbf += zD * blockIdx.z;
    if (resid) resid += zD * blockIdx.z;

    const int tid = threadIdx.x, lane = tid & 31, wid = tid >> 5;
    const int wm = wid >> 1, wn = wid & 1;              // warps 2x2; warp tile 64x64
    const int bM = blockIdx.y * BMT, bN = blockIdx.x * BNT;
    const uint32_t sbase = (uint32_t)__cvta_generic_to_shared(smem);

    // ldmatrix per-lane row/chunk components (same mapping as R5, warp grid re-decoded)
    const int l8 = lane & 7;
    const int a_row = wm * 64 + l8 + ((lane >> 3) & 1) * 8;   // + mt*16
    const int a_csel = lane >> 4;                             // k8 selector
    const int b_row = wn * 64 + l8 + (lane >> 4) * 8;         // + nt2*16
    const int b_csel = (lane >> 3) & 1;
    const int a_r7 = a_row & 7, b_r7 = b_row & 7;             // invariant under +16

    float acc[4][8][4];
    #pragma unroll
    for (int i = 0; i < 4; i++)
        #pragma unroll
        for (int j = 0; j < 8; j++)
            #pragma unroll
            for (int t = 0; t < 4; t++) acc[i][j][t] = 0.f;

    auto load_tile = [&](int kt, int s) {
        const int k0 = kt * BKT;
        const uint32_t sa = sbase + (uint32_t)(s * 2 * STG_B);
        const uint32_t sb = sa + STG_B;
        #pragma unroll
        for (int i = 0; i < 8; i++) {
            const int id = tid + i * 128;                // 1024 16B-chunks per operand
            const int row = id >> 3, c = id & 7;
            const uint32_t so = (uint32_t)(row * 128 + ((c ^ (row & 7)) << 4));
            cp16(sa + so, A + (size_t)(bM + row) * K + k0 + c * 8);
            cp16(sb + so, B + (size_t)(bN + row) * K + k0 + c * 8);
        }
        asm volatile("cp.async.commit_group;\n");
    };

    auto compute = [&](int s) {
        const uint32_t aB = sbase + (uint32_t)(s * 2 * STG_B);
        const uint32_t bB = aB + STG_B;
        #pragma unroll
        for (int ks = 0; ks < 4; ks++) {
            const int ac = ((ks * 2 + a_csel) ^ a_r7) << 4;
            const int bc = ((ks * 2 + b_csel) ^ b_r7) << 4;
            uint32_t af[4][4];
            #pragma unroll
            for (int mt = 0; mt < 4; mt++)
                ldm4(af[mt][0], af[mt][1], af[mt][2], af[mt][3],
                     aB + (uint32_t)((a_row + mt * 16) * 128 + ac));
            uint32_t bf[8][2];
            #pragma unroll
            for (int nt2 = 0; nt2 < 4; nt2++)
                ldm4(bf[2 * nt2][0], bf[2 * nt2][1], bf[2 * nt2 + 1][0], bf[2 * nt2 + 1][1],
                     bB + (uint32_t)((b_row + nt2 * 16) * 128 + bc));
            #pragma unroll
            for (int mt = 0; mt < 4; mt++)
                #pragma unroll
                for (int nt = 0; nt < 8; nt++)
                    mma_bf16(acc[mt][nt], af[mt], bf[nt]);
        }
    };

    const int KT = K / BKT;                             // >= 8 in all uses
    load_tile(0, 0);
    load_tile(1, 1);
    asm volatile("cp.async.wait_group 1;\n");
    __syncthreads();

    for (int kt = 0; kt < KT; kt++) {
        if (kt + 2 < KT) load_tile(kt + 2, (kt + 2) % NSTAGE);
        else asm volatile("cp.async.commit_group;\n");  // keep group count uniform
        compute(kt % NSTAGE);
        asm volatile("cp.async.wait_group 1;\n");
        __syncthreads();
    }

    // epilogue
    const int q4 = lane >> 2, cp2 = (lane & 3) * 2;
    #pragma unroll
    for (int mt = 0; mt < 4; mt++) {
        const int r0 = bM + wm * 64 + mt * 16 + q4;
        const int r1 = r0 + 8;
        const float rb0 = rowb ? rowb[r0] : 0.f;
        const float rb1 = rowb ? rowb[r1] : 0.f;
        #pragma unroll
        for (int nt = 0; nt < 8; nt++) {
            const int c = bN + wn * 64 + nt * 8 + cp2;
            float v00 = acc[mt][nt][0] * alpha + rb0;
            float v01 = acc[mt][nt][1] * alpha + rb0;
            float v10 = acc[mt][nt][2] * alpha + rb1;
            float v11 = acc[mt][nt][3] * alpha + rb1;
            if (colb) {
                const float cb0 = colb[c], cb1 = colb[c + 1];
                v00 += cb0; v01 += cb1; v10 += cb0; v11 += cb1;
            }
            if (resid) {
                float2 x0 = *reinterpret_cast<const float2*>(resid + (size_t)r0 * N + c);
                float2 x1 = *reinterpret_cast<const float2*>(resid + (size_t)r1 * N + c);
                v00 += x0.x; v01 += x0.y; v10 += x1.x; v11 += x1.y;
            }
            if (Df) {
                float2 o0; o0.x = v00; o0.y = v01;
                float2 o1; o1.x = v10; o1.y = v11;
                *reinterpret_cast<float2*>(Df + (size_t)r0 * N + c) = o0;
                *reinterpret_cast<float2*>(Df + (size_t)r1 * N + c) = o1;
            } else {
                *reinterpret_cast<__nv_bfloat162*>(Dbf + (size_t)r0 * N + c) =
                    __floats2bfloat162_rn(v00, v01);
                *reinterpret_cast<__nv_bfloat162*>(Dbf + (size_t)r1 * N + c) =
                    __floats2bfloat162_rn(v10, v11);
            }
        }
    }
}

// ---------------- fp32 -> bf16 conversion (all 4 weight matrices) ----------------
__global__ __launch_bounds__(256) void f2bf4_kernel(
    const float* __restrict__ s0, const float* __restrict__ s1,
    const float* __restrict__ s2, const float* __restrict__ s3,
    __nv_bfloat16* __restrict__ d0, __nv_bfloat16* __restrict__ d1,
    __nv_bfloat16* __restrict__ d2, __nv_bfloat16* __restrict__ d3)
{
    const float* src = (blockIdx.y == 0) ? s0 : (blockIdx.y == 1) ? s1
                     : (blockIdx.y == 2) ? s2 : s3;
    __nv_bfloat16* dst = (blockIdx.y == 0) ? d0 : (blockIdx.y == 1) ? d1
                        : (blockIdx.y == 2) ? d2 : d3;
    const int i = (blockIdx.x * 256 + threadIdx.x) * 4;
    float4 v = *reinterpret_cast<const float4*>(src + i);
    __nv_bfloat162 lo = __floats2bfloat162_rn(v.x, v.y);
    __nv_bfloat162 hi = __floats2bfloat162_rn(v.z, v.w);
    uint2 o; o.x = *reinterpret_cast<uint32_t*>(&lo); o.y = *reinterpret_cast<uint32_t*>(&hi);
    *reinterpret_cast<uint2*>(dst + i) = o;
}

// ---------------- GroupNorm -> bf16 token-major hn[b][n][c] ----------------
__global__ __launch_bounds__(1024) void gn_t_kernel(
    const float* __restrict__ x,
    const float* __restrict__ gamma,
    const float* __restrict__ beta)
{
    const int bg = blockIdx.x;
    const int b = bg / NGROUPS, g = bg % NGROUPS;
    const int len = CPG * NSP;
    const float* xp = x + ((size_t)b * CHN + g * CPG) * NSP;
    __nv_bfloat16* hp = g_hn + (size_t)b * NSP * CHN;

    float s = 0.f, ss = 0.f;
    for (int i = threadIdx.x * 4; i < len; i += blockDim.x * 4) {
        float4 v = *reinterpret_cast<const float4*>(xp + i);
        s  += v.x + v.y + v.z + v.w;
        ss += v.x * v.x + v.y * v.y + v.z * v.z + v.w * v.w;
    }
    __shared__ float rs[32], rss[32];
    #pragma unroll
    for (int o = 16; o; o >>= 1) {
        s  += __shfl_down_sync(0xffffffffu, s,  o);
        ss += __shfl_down_sync(0xffffffffu, ss, o);
    }
    const int warp = threadIdx.x >> 5, lane = threadIdx.x & 31;
    if (lane == 0) { rs[warp] = s; rss[warp] = ss; }
    __syncthreads();
    if (warp == 0) {
        s  = (lane < 32) ? rs[lane]  : 0.f;
        ss = (lane < 32) ? rss[lane] : 0.f;
        #pragma unroll
        for (int o = 16; o; o >>= 1) {
            s  += __shfl_down_sync(0xffffffffu, s,  o);
            ss += __shfl_down_sync(0xffffffffu, ss, o);
        }
        if (lane == 0) { rs[0] = s; rss[0] = ss; }
    }
    __syncthreads();
    const float mean = rs[0] / (float)len;
    const float var  = rss[0] / (float)len - mean * mean;
    const float inv  = rsqrtf(var + EPSV);
    __syncthreads();

    __shared__ float tile[CPG][257];
    const int cc_w = threadIdx.x & 15;
    const float ga = gamma[g * CPG + cc_w] * inv;
    const float be = beta[g * CPG + cc_w];

    for (int t16 = 0; t16 < 16; t16++) {
        const int n0 = t16 * 256;
        #pragma unroll
        for (int j = 0; j < 4; j++) {
            const int idx = threadIdx.x + j * 1024;
            const int cc = idx >> 8, nn = idx & 255;
            tile[cc][nn] = xp[(size_t)cc * NSP + n0 + nn];
        }
        __syncthreads();
        #pragma unroll
        for (int j = 0; j < 4; j++) {
            const int idx = threadIdx.x + j * 1024;
            const int n = idx >> 4;
            hp[(size_t)(n0 + n) * CHN + g * CPG + cc_w] =
                __float2bfloat16((tile[cc_w][n] - mean) * ga + be);
        }
        __syncthreads();
    }
}

// ---------------- row softmax: S fp32 -> P bf16 ----------------
__global__ __launch_bounds__(256) void softmax_kernel(
    const float* __restrict__ Sbase, __nv_bfloat16* __restrict__ Pbase)
{
    const float* p = Sbase + (size_t)blockIdx.x * NSP;
    __nv_bfloat16* po = Pbase + (size_t)blockIdx.x * NSP;
    const int t = threadIdx.x;
    const int warp = t >> 5, lane = t & 31;
    __shared__ float red[8];

    float4 v[4];
    float mx = -3.4e38f;
    #pragma unroll
    for (int l = 0; l < 4; l++) {
        v[l] = *reinterpret_cast<const float4*>(p + l * 1024 + t * 4);
        mx = fmaxf(mx, fmaxf(fmaxf(v[l].x, v[l].y), fmaxf(v[l].z, v[l].w)));
    }
    #pragma unroll
    for (int o = 16; o; o >>= 1) mx = fmaxf(mx, __shfl_xor_sync(0xffffffffu, mx, o));
    if (lane == 0) red[warp] = mx;
    __syncthreads();
    mx = red[0];
    #pragma unroll
    for (int w = 1; w < 8; w++) mx = fmaxf(mx, red[w]);
    __syncthreads();

    float s = 0.f;
    #pragma unroll
    for (int l = 0; l < 4; l++) {
        v[l].x = __expf(v[l].x - mx); v[l].y = __expf(v[l].y - mx);
        v[l].z = __expf(v[l].z - mx); v[l].w = __expf(v[l].w - mx);
        s += v[l].x + v[l].y + v[l].z + v[l].w;
    }
    #pragma unroll
    for (int o = 16; o; o >>= 1) s += __shfl_xor_sync(0xffffffffu, s, o);
    if (lane == 0) red[warp] = s;
    __syncthreads();
    s = red[0];
    #pragma unroll
    for (int w = 1; w < 8; w++) s += red[w];
    const float inv = 1.f / s;
    #pragma unroll
    for (int l = 0; l < 4; l++) {
        __nv_bfloat162 lo = __floats2bfloat162_rn(v[l].x * inv, v[l].y * inv);
        __nv_bfloat162 hi = __floats2bfloat162_rn(v[l].z * inv, v[l].w * inv);
        uint2 o; o.x = *reinterpret_cast<uint32_t*>(&lo); o.y = *reinterpret_cast<uint32_t*>(&hi);
        *reinterpret_cast<uint2*>(po + l * 1024 + t * 4) = o;
    }
}

// ---------------- launch ----------------
extern "C" void kernel_launch(void* const* d_in, const int* in_sizes, int n_in,
                              void* d_out, int out_size)
{
    const float* x        = (const float*)d_in[0];
    const float* gn_gamma = (const float*)d_in[1];
    const float* gn_beta  = (const float*)d_in[2];
    const float* q_w      = (const float*)d_in[3];
    const float* q_b      = (const float*)d_in[4];
    const float* k_w      = (const float*)d_in[5];
    const float* k_b      = (const float*)d_in[6];
    const float* v_w      = (const float*)d_in[7];
    const float* v_b      = (const float*)d_in[8];
    const float* proj_w   = (const float*)d_in[9];
    const float* proj_b   = (const float*)d_in[10];
    float* out = (float*)d_out;

    __nv_bfloat16 *hn, *q, *k, *v, *h, *P, *wq, *wk, *wv, *wp;
    float *S;
    cudaGetSymbolAddress((void**)&hn, g_hn);
    cudaGetSymbolAddress((void**)&q,  g_q);
    cudaGetSymbolAddress((void**)&k,  g_k);
    cudaGetSymbolAddress((void**)&v,  g_v);
    cudaGetSymbolAddress((void**)&h,  g_h);
    cudaGetSymbolAddress((void**)&S,  g_S);
    cudaGetSymbolAddress((void**)&P,  g_P);
    cudaGetSymbolAddress((void**)&wq, g_wq);
    cudaGetSymbolAddress((void**)&wk, g_wk);
    cudaGetSymbolAddress((void**)&wv, g_wv);
    cudaGetSymbolAddress((void**)&wp, g_wp);

    cudaFuncSetAttribute(bgemm_nt, cudaFuncAttributeMaxDynamicSharedMemorySize, SMEM_BYTES);

    const size_t CN = (size_t)CHN * NSP;
    const size_t NN = (size_t)NSP * NSP;

    // 0) all four weight matrices -> bf16, one launch
    f2bf4_kernel<<<dim3(CHN * CHN / 1024, 4), 256>>>(q_w, k_w, v_w, proj_w, wq, wk, wv, wp);

    // 1) GroupNorm -> hn bf16 [b][n][c]
    gn_t_kernel<<<BATCH * NGROUPS, 1024>>>(x, gn_gamma, gn_beta);

    // 2) q[n][co] = hn[n][:] . wq[co][:] + q_b  (M=4096,N=512,K=512), bf16 out
    bgemm_nt<<<dim3(CHN / BNT, NSP / BMT, BATCH), 128, SMEM_BYTES>>>(
        hn, wq, nullptr, q, nullptr, q_b, nullptr, NSP, CHN, CHN, 1.f, CN, 0, CN);
    bgemm_nt<<<dim3(CHN / BNT, NSP / BMT, BATCH), 128, SMEM_BYTES>>>(
        hn, wk, nullptr, k, nullptr, k_b, nullptr, NSP, CHN, CHN, 1.f, CN, 0, CN);
    // v[c][n] = wv[c][:] . hn[n][:] + v_b  (M=512,N=4096,K=512), bf16 out
    bgemm_nt<<<dim3(NSP / BNT, CHN / BMT, BATCH), 128, SMEM_BYTES>>>(
        wv, hn, nullptr, v, v_b, nullptr, nullptr, CHN, NSP, CHN, 1.f, 0, CN, CN);

    // 3) S = scale * q . k^T  (M=N=4096,K=512), fp32 out
    bgemm_nt<<<dim3(NSP / BNT, NSP / BMT, BATCH), 128, SMEM_BYTES>>>(
        q, k, S, nullptr, nullptr, nullptr, nullptr, NSP, NSP, CHN, SM_SCALE, CN, CN, NN);

    // 4) softmax rows -> P bf16
    softmax_kernel<<<BATCH * NSP, 256>>>(S, P);

    // 5) h[i][c] = P[i][:] . v[c][:]  (M=4096,N=512,K=4096), bf16 out
    bgemm_nt<<<dim3(CHN / BNT, NSP / BMT, BATCH), 128, SMEM_BYTES>>>(
        P, v, nullptr, h, nullptr, nullptr, nullptr, NSP, CHN, NSP, 1.f, NN, CN, CN);

    // 6) out[co][n] = wp[co][:] . h[n][:] + proj_b[co] + x[co][n], fp32 out
    bgemm_nt<<<dim3(NSP / BNT, CHN / BMT, BATCH), 128, SMEM_BYTES>>>(
        wp, h, out, nullptr, proj_b, nullptr, x, CHN, NSP, CHN, 1.f, 0, CN, CN);
}